// round 10
// baseline (speedup 1.0000x reference)
#include <cuda_runtime.h>
#include <cuda_bf16.h>
#include <math.h>
#include <stdint.h>

#define N_NODES 65536
#define N_EDGES 524288
#define HIDDEN 128
#define OUTDIM 10
#define NUM_GRAPHS 64
#define SLOT_CAP 64

// ---------------- scratch (device globals; no allocation allowed) ----------
__device__ __align__(16) static float    g_h0[(size_t)N_NODES * HIDDEN];
__device__ __align__(16) static float    g_h1[(size_t)N_NODES * HIDDEN];
__device__ static int      g_deg[N_NODES];
__device__ static int      g_slots[(size_t)N_NODES * SLOT_CAP];
__device__ static float    g_gsum[NUM_GRAPHS * HIDDEN];
__device__ static float    g_gcnt[NUM_GRAPHS];
__device__ static int      g_is64;
__device__ static unsigned int g_ctr[4];
__device__ __align__(16) static uint32_t g_whi[3][HIDDEN * 64];
__device__ __align__(16) static uint32_t g_wlo[3][HIDDEN * 64];

// ---------------- helpers ----------------------------------------------------
__device__ __forceinline__ int kperm(int w) {
    return (w & ~7) | (((w & 3) << 1) | ((w >> 2) & 1));
}

__device__ __forceinline__ void bf16_split(float v, uint16_t& h, uint16_t& l) {
    __nv_bfloat16 hb = __float2bfloat16(v);
    float r = v - __bfloat162float(hb);
    __nv_bfloat16 lb = __float2bfloat16(r);
    h = __bfloat16_as_ushort(hb);
    l = __bfloat16_as_ushort(lb);
}

__device__ __forceinline__ float elu_fast(float v) {
    return v > 0.0f ? v : (__expf(v) - 1.0f);
}

__device__ __forceinline__ void mma_bf16(float* c, uint32_t a0, uint32_t a1,
                                         uint32_t a2, uint32_t a3,
                                         uint32_t b0, uint32_t b1) {
    asm volatile(
        "mma.sync.aligned.m16n8k16.row.col.f32.bf16.bf16.f32 "
        "{%0,%1,%2,%3}, {%4,%5,%6,%7}, {%8,%9}, {%0,%1,%2,%3};"
        : "+f"(c[0]), "+f"(c[1]), "+f"(c[2]), "+f"(c[3])
        : "r"(a0), "r"(a1), "r"(a2), "r"(a3), "r"(b0), "r"(b1));
}

// ---------------- index dtype detection (1 warp, parallel) -------------------
__global__ void detect_kernel(const unsigned int* __restrict__ w) {
    int lane = threadIdx.x;
    bool zero = true;
#pragma unroll
    for (int j = 0; j < 4; j++) {
        if (w[1 + 2 * (lane + 32 * j)] != 0u) zero = false;
    }
    unsigned int mask = __ballot_sync(0xffffffffu, zero);
    if (lane == 0) g_is64 = (mask == 0xffffffffu) ? 1 : 0;
}

__device__ __forceinline__ int load_idx(const void* p, int i, int is64) {
    if (is64) return (int)((const long long*)p)[i];
    return ((const int*)p)[i];
}

// ---------------- prep: zero scratch + W split (fused) ------------------------
__global__ void prep_kernel(const float* __restrict__ W1,
                            const float* __restrict__ W2,
                            const float* __restrict__ W3) {
    int i = blockIdx.x * blockDim.x + threadIdx.x;
    if (i < N_NODES) g_deg[i] = 0;
    if (i < NUM_GRAPHS * HIDDEN) g_gsum[i] = 0.0f;
    if (i < NUM_GRAPHS) g_gcnt[i] = 0.0f;
    if (i < 4) g_ctr[i] = 0;
    if (i < 3 * HIDDEN * 64) {
        int layer = i / (HIDDEN * 64);
        int rem = i - layer * (HIDDEN * 64);
        int n = rem >> 6, w = rem & 63;
        const float* W = (layer == 0) ? W1 : (layer == 1) ? W2 : W3;
        float v0 = __ldg(W + (2 * w) * HIDDEN + n);
        float v1 = __ldg(W + (2 * w + 1) * HIDDEN + n);
        uint16_t h0, l0, h1, l1;
        bf16_split(v0, h0, l0);
        bf16_split(v1, h1, l1);
        int pos = n * 64 + kperm(w);
        g_whi[layer][pos] = (uint32_t)h0 | ((uint32_t)h1 << 16);
        g_wlo[layer][pos] = (uint32_t)l0 | ((uint32_t)l1 << 16);
    }
}

// ---------------- bucketed inverse adjacency ---------------------------------
__global__ void build_kernel(const void* __restrict__ src,
                             const void* __restrict__ dst) {
    int e = blockIdx.x * blockDim.x + threadIdx.x;
    if (e >= N_EDGES) return;
    int is64 = g_is64;
    int d = load_idx(dst, e, is64);
    int s = load_idx(src, e, is64);
    int pos = atomicAdd(&g_deg[d], 1);
    if (pos < SLOT_CAP) g_slots[(size_t)d * SLOT_CAP + pos] = s;
}

// ---------------- fused gather + bf16x3 mma GEMM layer ------------------------
// Persistent CTAs steal 64-row tiles from a counter. Per tile: warps gather 8
// nodes each (neighbor sum in regs), split bf16 -> STS into A smem, sync, then
// R7-proven MMA mainloop + bias + ELU epilogue.
#define AS_STR 68
#define SM_AH 0
#define SM_AL (64 * AS_STR)
#define SM_WH (2 * 64 * AS_STR)
#define SM_WL (2 * 64 * AS_STR + 128 * AS_STR)
#define GEMM_SMEM_WORDS (2 * 64 * AS_STR + 2 * 128 * AS_STR)
#define GEMM_SMEM_BYTES (GEMM_SMEM_WORDS * 4)
#define GEMM_GRID 296
#define NUM_TILES (N_NODES / 64)

__global__ void __launch_bounds__(256, 2)
layer_kernel(const float* __restrict__ hin,
             const uint32_t* __restrict__ Wh, const uint32_t* __restrict__ Wl,
             const float* __restrict__ b, float* __restrict__ out,
             unsigned int* __restrict__ ctr) {
    extern __shared__ __align__(16) uint32_t smem[];
    __shared__ unsigned int s_tile;
    int tid = threadIdx.x;
    int lane = tid & 31, wid = tid >> 5;
    int gq = lane >> 2, tq = lane & 3;
    int warp_m = wid & 1, warp_n = wid >> 1;
    const int mBase = warp_m * 32;
    const int nBase = warp_n * 32;

    // ---- stage W planes once ----
    {
        const uint4* src_h = (const uint4*)Wh;
        const uint4* src_l = (const uint4*)Wl;
        for (int i = tid; i < 128 * 16; i += 256) {
            int n = i >> 4, c4 = i & 15;
            *(uint4*)(smem + SM_WH + n * AS_STR + c4 * 4) = __ldg(src_h + i);
            *(uint4*)(smem + SM_WL + n * AS_STR + c4 * 4) = __ldg(src_l + i);
        }
    }
    if (tid == 0) s_tile = atomicAdd(ctr, 1);
    __syncthreads();

    int p0 = kperm(2 * lane), p1 = kperm(2 * lane + 1);

    while (true) {
        unsigned int tile = s_tile;
        if (tile >= NUM_TILES) break;
        size_t rowBase = (size_t)tile * 64;

        // ---- gather phase: warp handles 8 nodes ----
        int node0 = (int)rowBase + wid * 8;
#pragma unroll
        for (int j = 0; j < 8; j++) {
            int node = node0 + j;
            int deg = g_deg[node];
            if (deg > SLOT_CAP) deg = SLOT_CAP;
            const int* slots = g_slots + (size_t)node * SLOT_CAP;
            int s0 = (lane < deg) ? slots[lane] : 0;
            int s1 = (32 + lane < deg) ? slots[32 + lane] : 0;
            float4 acc = make_float4(0.f, 0.f, 0.f, 0.f);
            for (int i = 0; i < deg; i++) {
                int s = __shfl_sync(0xffffffffu, (i < 32) ? s0 : s1, i & 31);
                float4 v = __ldg((const float4*)(hin + (size_t)s * HIDDEN) + lane);
                acc.x += v.x; acc.y += v.y; acc.z += v.z; acc.w += v.w;
            }
            uint16_t hx, lx, hy, ly, hz, lz, hw, lw;
            bf16_split(acc.x, hx, lx);
            bf16_split(acc.y, hy, ly);
            bf16_split(acc.z, hz, lz);
            bf16_split(acc.w, hw, lw);
            int r = wid * 8 + j;
            smem[SM_AH + r * AS_STR + p0] = (uint32_t)hx | ((uint32_t)hy << 16);
            smem[SM_AH + r * AS_STR + p1] = (uint32_t)hz | ((uint32_t)hw << 16);
            smem[SM_AL + r * AS_STR + p0] = (uint32_t)lx | ((uint32_t)ly << 16);
            smem[SM_AL + r * AS_STR + p1] = (uint32_t)lz | ((uint32_t)lw << 16);
        }
        __syncthreads();
        if (tid == 0) s_tile = atomicAdd(ctr, 1);

        // ---- MMA mainloop ----
        float acc[2][4][4];
#pragma unroll
        for (int mi = 0; mi < 2; mi++)
#pragma unroll
            for (int ni = 0; ni < 4; ni++)
#pragma unroll
                for (int r = 0; r < 4; r++) acc[mi][ni][r] = 0.0f;

#pragma unroll
        for (int ks = 0; ks < 8; ks++) {
            int kw = ks * 8 + 2 * tq;
            uint2 ah[2][2], al[2][2];
#pragma unroll
            for (int mi = 0; mi < 2; mi++) {
                int r = mBase + mi * 16 + gq;
                ah[mi][0] = *(const uint2*)(smem + SM_AH + r * AS_STR + kw);
                ah[mi][1] = *(const uint2*)(smem + SM_AH + (r + 8) * AS_STR + kw);
                al[mi][0] = *(const uint2*)(smem + SM_AL + r * AS_STR + kw);
                al[mi][1] = *(const uint2*)(smem + SM_AL + (r + 8) * AS_STR + kw);
            }
            uint2 bh[4], bl[4];
#pragma unroll
            for (int ni = 0; ni < 4; ni++) {
                int c = nBase + ni * 8 + gq;
                bh[ni] = *(const uint2*)(smem + SM_WH + c * AS_STR + kw);
                bl[ni] = *(const uint2*)(smem + SM_WL + c * AS_STR + kw);
            }
#pragma unroll
            for (int mi = 0; mi < 2; mi++)
#pragma unroll
                for (int ni = 0; ni < 4; ni++) {
                    mma_bf16(acc[mi][ni], ah[mi][0].x, ah[mi][1].x, ah[mi][0].y, ah[mi][1].y,
                             bh[ni].x, bh[ni].y);
                    mma_bf16(acc[mi][ni], ah[mi][0].x, ah[mi][1].x, ah[mi][0].y, ah[mi][1].y,
                             bl[ni].x, bl[ni].y);
                    mma_bf16(acc[mi][ni], al[mi][0].x, al[mi][1].x, al[mi][0].y, al[mi][1].y,
                             bh[ni].x, bh[ni].y);
                }
        }

        // ---- epilogue: bias + fast ELU + store ----
#pragma unroll
        for (int mi = 0; mi < 2; mi++) {
            int r0 = mBase + mi * 16 + gq;
#pragma unroll
            for (int ni = 0; ni < 4; ni++) {
                int c0 = nBase + ni * 8 + 2 * tq;
                float2 bb = __ldg((const float2*)(b + c0));
                float v0 = elu_fast(acc[mi][ni][0] + bb.x);
                float v1 = elu_fast(acc[mi][ni][1] + bb.y);
                float v2 = elu_fast(acc[mi][ni][2] + bb.x);
                float v3 = elu_fast(acc[mi][ni][3] + bb.y);
                *(float2*)(out + (rowBase + r0) * HIDDEN + c0) = make_float2(v0, v1);
                *(float2*)(out + (rowBase + r0 + 8) * HIDDEN + c0) = make_float2(v2, v3);
            }
        }
        __syncthreads();   // A smem free for next tile's gather
    }
}

// ---------------- graph readout (sums + counts fused) -------------------------
__global__ void readout_kernel(const float* __restrict__ h,
                               const void* __restrict__ gid) {
    int t = threadIdx.x;
    int base = blockIdx.x * 128;
    int is64 = g_is64;
    int cur = load_idx(gid, base, is64);
    float acc = 0.0f;
    int runlen = 0;
    for (int n = 0; n < 128; n++) {
        int node = base + n;
        int g = load_idx(gid, node, is64);
        if (g != cur) {
            atomicAdd(&g_gsum[cur * HIDDEN + t], acc);
            if (t == 0) atomicAdd(&g_gcnt[cur], (float)runlen);
            acc = 0.0f; runlen = 0; cur = g;
        }
        acc += h[(size_t)node * HIDDEN + t];
        runlen++;
    }
    atomicAdd(&g_gsum[cur * HIDDEN + t], acc);
    if (t == 0) atomicAdd(&g_gcnt[cur], (float)runlen);
}

__global__ void classifier_kernel(const float* __restrict__ Wc,
                                  const float* __restrict__ bc,
                                  float* __restrict__ out) {
    int t = blockIdx.x * blockDim.x + threadIdx.x;
    if (t >= NUM_GRAPHS * OUTDIM) return;
    int g = t / OUTDIM, o = t % OUTDIM;
    float c = fmaxf(g_gcnt[g], 1.0f);
    float inv = 1.0f / c;
    float acc = bc[o];
#pragma unroll 8
    for (int k = 0; k < HIDDEN; k++)
        acc += g_gsum[g * HIDDEN + k] * inv * Wc[k * OUTDIM + o];
    out[t] = acc;
}

// ---------------- launch -------------------------------------------------------
extern "C" void kernel_launch(void* const* d_in, const int* in_sizes, int n_in,
                              void* d_out, int out_size) {
    const float* features = (const float*)d_in[0];
    const void*  src      = d_in[1];
    const void*  dst      = d_in[2];
    const void*  gids     = d_in[3];
    const float* W1 = (const float*)d_in[4];
    const float* b1 = (const float*)d_in[5];
    const float* W2 = (const float*)d_in[6];
    const float* b2 = (const float*)d_in[7];
    const float* W3 = (const float*)d_in[8];
    const float* b3 = (const float*)d_in[9];
    const float* Wc = (const float*)d_in[10];
    const float* bc = (const float*)d_in[11];
    float* out = (float*)d_out;

    float* h0;     cudaGetSymbolAddress((void**)&h0, g_h0);
    float* h1;     cudaGetSymbolAddress((void**)&h1, g_h1);
    uint32_t* whi; cudaGetSymbolAddress((void**)&whi, g_whi);
    uint32_t* wlo; cudaGetSymbolAddress((void**)&wlo, g_wlo);
    unsigned int* ctr; cudaGetSymbolAddress((void**)&ctr, g_ctr);

    cudaFuncSetAttribute(layer_kernel,
                         cudaFuncAttributeMaxDynamicSharedMemorySize, GEMM_SMEM_BYTES);

    detect_kernel<<<1, 32>>>((const unsigned int*)src);
    prep_kernel<<<N_NODES / 256, 256>>>(W1, W2, W3);
    build_kernel<<<N_EDGES / 256, 256>>>(src, dst);

    const int WSZ = HIDDEN * 64;

    // double-buffered: features -> h0 -> h1 -> h0
    layer_kernel<<<GEMM_GRID, 256, GEMM_SMEM_BYTES>>>(features, whi, wlo, b1, h0, ctr + 0);
    layer_kernel<<<GEMM_GRID, 256, GEMM_SMEM_BYTES>>>(h0, whi + WSZ, wlo + WSZ, b2, h1, ctr + 1);
    layer_kernel<<<GEMM_GRID, 256, GEMM_SMEM_BYTES>>>(h1, whi + 2 * WSZ, wlo + 2 * WSZ, b3, h0, ctr + 2);

    readout_kernel<<<N_NODES / 128, 128>>>(h0, gids);
    classifier_kernel<<<1, NUM_GRAPHS * OUTDIM>>>(Wc, bc, out);
}

// round 11
// speedup vs baseline: 1.7012x; 1.7012x over previous
#include <cuda_runtime.h>
#include <cuda_fp16.h>
#include <math.h>
#include <stdint.h>

#define N_NODES 65536
#define N_EDGES 524288
#define HIDDEN 128
#define OUTDIM 10
#define NUM_GRAPHS 64
#define SLOT_CAP 64

// ---------------- scratch (device globals; no allocation allowed) ----------
// A plane: fp16 pairs, k-word-permuted, 64 words (128 fp16) per node row.
__device__ __align__(16) static uint32_t g_ah[(size_t)N_NODES * 64];
__device__ __align__(16) static float    g_h[(size_t)N_NODES * HIDDEN];
__device__ static int      g_deg[N_NODES];
__device__ static int      g_slots[(size_t)N_NODES * SLOT_CAP];
__device__ static float    g_gsum[NUM_GRAPHS * HIDDEN];
__device__ static float    g_gcnt[NUM_GRAPHS];
__device__ static int      g_is64;
// W planes: [layer][n*64 + permuted k word], fp16 pairs, hi/lo split
__device__ __align__(16) static uint32_t g_whi[3][HIDDEN * 64];
__device__ __align__(16) static uint32_t g_wlo[3][HIDDEN * 64];

// ---------------- helpers ----------------------------------------------------
__device__ __forceinline__ int kperm(int w) {
    return (w & ~7) | (((w & 3) << 1) | ((w >> 2) & 1));
}

__device__ __forceinline__ void fp16_split(float v, uint16_t& h, uint16_t& l) {
    __half hb = __float2half_rn(v);
    float r = v - __half2float(hb);
    __half lb = __float2half_rn(r);
    h = __half_as_ushort(hb);
    l = __half_as_ushort(lb);
}

__device__ __forceinline__ float elu_fast(float v) {
    return v > 0.0f ? v : (__expf(v) - 1.0f);
}

__device__ __forceinline__ void mma_fp16(float* c, uint32_t a0, uint32_t a1,
                                         uint32_t a2, uint32_t a3,
                                         uint32_t b0, uint32_t b1) {
    asm volatile(
        "mma.sync.aligned.m16n8k16.row.col.f32.f16.f16.f32 "
        "{%0,%1,%2,%3}, {%4,%5,%6,%7}, {%8,%9}, {%0,%1,%2,%3};"
        : "+f"(c[0]), "+f"(c[1]), "+f"(c[2]), "+f"(c[3])
        : "r"(a0), "r"(a1), "r"(a2), "r"(a3), "r"(b0), "r"(b1));
}

// ---------------- index dtype detection (1 warp, parallel) -------------------
__global__ void detect_kernel(const unsigned int* __restrict__ w) {
    int lane = threadIdx.x;
    bool zero = true;
#pragma unroll
    for (int j = 0; j < 4; j++) {
        if (w[1 + 2 * (lane + 32 * j)] != 0u) zero = false;
    }
    unsigned int mask = __ballot_sync(0xffffffffu, zero);
    if (lane == 0) g_is64 = (mask == 0xffffffffu) ? 1 : 0;
}

__device__ __forceinline__ int load_idx(const void* p, int i, int is64) {
    if (is64) return (int)((const long long*)p)[i];
    return ((const int*)p)[i];
}

// ---------------- prep: zero scratch + W fp16 split (fused) ------------------
__global__ void prep_kernel(const float* __restrict__ W1,
                            const float* __restrict__ W2,
                            const float* __restrict__ W3) {
    int i = blockIdx.x * blockDim.x + threadIdx.x;
    if (i < N_NODES) g_deg[i] = 0;
    if (i < NUM_GRAPHS * HIDDEN) g_gsum[i] = 0.0f;
    if (i < NUM_GRAPHS) g_gcnt[i] = 0.0f;
    if (i < 3 * HIDDEN * 64) {
        int layer = i / (HIDDEN * 64);
        int rem = i - layer * (HIDDEN * 64);
        int n = rem >> 6, w = rem & 63;
        const float* W = (layer == 0) ? W1 : (layer == 1) ? W2 : W3;
        float v0 = __ldg(W + (2 * w) * HIDDEN + n);
        float v1 = __ldg(W + (2 * w + 1) * HIDDEN + n);
        uint16_t h0, l0, h1, l1;
        fp16_split(v0, h0, l0);
        fp16_split(v1, h1, l1);
        int pos = n * 64 + kperm(w);
        g_whi[layer][pos] = (uint32_t)h0 | ((uint32_t)h1 << 16);
        g_wlo[layer][pos] = (uint32_t)l0 | ((uint32_t)l1 << 16);
    }
}

// ---------------- bucketed inverse adjacency ---------------------------------
__global__ void build_kernel(const void* __restrict__ src,
                             const void* __restrict__ dst) {
    int e = blockIdx.x * blockDim.x + threadIdx.x;
    if (e >= N_EDGES) return;
    int is64 = g_is64;
    int d = load_idx(dst, e, is64);
    int s = load_idx(src, e, is64);
    int pos = atomicAdd(&g_deg[d], 1);
    if (pos < SLOT_CAP) g_slots[(size_t)d * SLOT_CAP + pos] = s;
}

// ---------------- gather-sum -> single fp16 A plane (k-word permuted) --------
__global__ void gather_kernel(const float* __restrict__ hin,
                              uint32_t* __restrict__ ah) {
    int w = (blockIdx.x * blockDim.x + threadIdx.x) >> 5;
    int lane = threadIdx.x & 31;
    if (w >= N_NODES) return;
    int deg = g_deg[w];
    if (deg > SLOT_CAP) deg = SLOT_CAP;
    const int* slots = g_slots + (size_t)w * SLOT_CAP;
    int s0 = (lane < deg) ? slots[lane] : 0;
    int s1 = (32 + lane < deg) ? slots[32 + lane] : 0;
    float4 acc = make_float4(0.f, 0.f, 0.f, 0.f);
    for (int i = 0; i < deg; i++) {
        int s = __shfl_sync(0xffffffffu, (i < 32) ? s0 : s1, i & 31);
        float4 v = __ldg((const float4*)(hin + (size_t)s * HIDDEN) + lane);
        acc.x += v.x; acc.y += v.y; acc.z += v.z; acc.w += v.w;
    }
    __half hx = __float2half_rn(acc.x);
    __half hy = __float2half_rn(acc.y);
    __half hz = __float2half_rn(acc.z);
    __half hw = __float2half_rn(acc.w);
    size_t rowOff = (size_t)w * 64;
    int p0 = kperm(2 * lane), p1 = kperm(2 * lane + 1);
    ah[rowOff + p0] = (uint32_t)__half_as_ushort(hx) | ((uint32_t)__half_as_ushort(hy) << 16);
    ah[rowOff + p1] = (uint32_t)__half_as_ushort(hz) | ((uint32_t)__half_as_ushort(hw) << 16);
}

// ---------------- persistent fp16x2 mma GEMM ----------------------------------
// 296 CTAs loop over 64-row tiles. 256 threads = 8 warps (2M x 4N), warp 32x32.
// D = Ah*(Wh + Wl): 2 MMA per fragment pair (vs 3 in bf16x3).
#define AS_STR 68
#define SM_AH 0
#define SM_WH (64 * AS_STR)
#define SM_WL (64 * AS_STR + 128 * AS_STR)
#define GEMM_SMEM_WORDS (64 * AS_STR + 2 * 128 * AS_STR)
#define GEMM_SMEM_BYTES (GEMM_SMEM_WORDS * 4)
#define GEMM_GRID 296
#define NUM_TILES (N_NODES / 64)

__global__ void __launch_bounds__(256, 2)
gemm_tc_kernel(const uint32_t* __restrict__ Ah,
               const uint32_t* __restrict__ Wh, const uint32_t* __restrict__ Wl,
               const float* __restrict__ b, float* __restrict__ out) {
    extern __shared__ __align__(16) uint32_t smem[];
    int tid = threadIdx.x;
    int lane = tid & 31, wid = tid >> 5;
    int gq = lane >> 2, tq = lane & 3;
    int warp_m = wid & 1, warp_n = wid >> 1;
    const int mBase = warp_m * 32;
    const int nBase = warp_n * 32;

    // ---- stage W planes once ----
    {
        const uint4* src_h = (const uint4*)Wh;
        const uint4* src_l = (const uint4*)Wl;
        for (int i = tid; i < 128 * 16; i += 256) {
            int n = i >> 4, c4 = i & 15;
            *(uint4*)(smem + SM_WH + n * AS_STR + c4 * 4) = __ldg(src_h + i);
            *(uint4*)(smem + SM_WL + n * AS_STR + c4 * 4) = __ldg(src_l + i);
        }
    }

    int tile = blockIdx.x;
    uint4 pa[4];
    if (tile < NUM_TILES) {
        const uint4* src = (const uint4*)(Ah + (size_t)tile * 64 * 64);
#pragma unroll
        for (int j = 0; j < 4; j++) pa[j] = __ldg(src + tid + 256 * j);
    }
    __syncthreads();

    while (tile < NUM_TILES) {
        // ---- commit prefetched A to SMEM ----
#pragma unroll
        for (int j = 0; j < 4; j++) {
            int i = tid + 256 * j;
            int r = i >> 4, c4 = i & 15;
            *(uint4*)(smem + SM_AH + r * AS_STR + c4 * 4) = pa[j];
        }
        __syncthreads();

        // ---- prefetch next tile's A (overlaps mainloop) ----
        int next = tile + GEMM_GRID;
        if (next < NUM_TILES) {
            const uint4* src = (const uint4*)(Ah + (size_t)next * 64 * 64);
#pragma unroll
            for (int j = 0; j < 4; j++) pa[j] = __ldg(src + tid + 256 * j);
        }

        float acc[2][4][4];
#pragma unroll
        for (int mi = 0; mi < 2; mi++)
#pragma unroll
            for (int ni = 0; ni < 4; ni++)
#pragma unroll
                for (int r = 0; r < 4; r++) acc[mi][ni][r] = 0.0f;

#pragma unroll
        for (int ks = 0; ks < 8; ks++) {
            int kw = ks * 8 + 2 * tq;
            uint2 ah2[2][2];
#pragma unroll
            for (int mi = 0; mi < 2; mi++) {
                int r = mBase + mi * 16 + gq;
                ah2[mi][0] = *(const uint2*)(smem + SM_AH + r * AS_STR + kw);
                ah2[mi][1] = *(const uint2*)(smem + SM_AH + (r + 8) * AS_STR + kw);
            }
            uint2 bh[4], bl[4];
#pragma unroll
            for (int ni = 0; ni < 4; ni++) {
                int c = nBase + ni * 8 + gq;
                bh[ni] = *(const uint2*)(smem + SM_WH + c * AS_STR + kw);
                bl[ni] = *(const uint2*)(smem + SM_WL + c * AS_STR + kw);
            }
#pragma unroll
            for (int mi = 0; mi < 2; mi++)
#pragma unroll
                for (int ni = 0; ni < 4; ni++) {
                    mma_fp16(acc[mi][ni], ah2[mi][0].x, ah2[mi][1].x, ah2[mi][0].y, ah2[mi][1].y,
                             bh[ni].x, bh[ni].y);
                    mma_fp16(acc[mi][ni], ah2[mi][0].x, ah2[mi][1].x, ah2[mi][0].y, ah2[mi][1].y,
                             bl[ni].x, bl[ni].y);
                }
        }

        // ---- epilogue: bias + fast ELU + store ----
        size_t rowBase = (size_t)tile * 64;
#pragma unroll
        for (int mi = 0; mi < 2; mi++) {
            int r0 = mBase + mi * 16 + gq;
#pragma unroll
            for (int ni = 0; ni < 4; ni++) {
                int c0 = nBase + ni * 8 + 2 * tq;
                float2 bb = __ldg((const float2*)(b + c0));
                float v0 = elu_fast(acc[mi][ni][0] + bb.x);
                float v1 = elu_fast(acc[mi][ni][1] + bb.y);
                float v2 = elu_fast(acc[mi][ni][2] + bb.x);
                float v3 = elu_fast(acc[mi][ni][3] + bb.y);
                *(float2*)(out + (rowBase + r0) * HIDDEN + c0) = make_float2(v0, v1);
                *(float2*)(out + (rowBase + r0 + 8) * HIDDEN + c0) = make_float2(v2, v3);
            }
        }
        __syncthreads();
        tile = next;
    }
}

// ---------------- graph readout (sums + counts fused) -------------------------
__global__ void readout_kernel(const float* __restrict__ h,
                               const void* __restrict__ gid) {
    int t = threadIdx.x;
    int base = blockIdx.x * 128;
    int is64 = g_is64;
    int cur = load_idx(gid, base, is64);
    float acc = 0.0f;
    int runlen = 0;
    for (int n = 0; n < 128; n++) {
        int node = base + n;
        int g = load_idx(gid, node, is64);
        if (g != cur) {
            atomicAdd(&g_gsum[cur * HIDDEN + t], acc);
            if (t == 0) atomicAdd(&g_gcnt[cur], (float)runlen);
            acc = 0.0f; runlen = 0; cur = g;
        }
        acc += h[(size_t)node * HIDDEN + t];
        runlen++;
    }
    atomicAdd(&g_gsum[cur * HIDDEN + t], acc);
    if (t == 0) atomicAdd(&g_gcnt[cur], (float)runlen);
}

__global__ void classifier_kernel(const float* __restrict__ Wc,
                                  const float* __restrict__ bc,
                                  float* __restrict__ out) {
    int t = blockIdx.x * blockDim.x + threadIdx.x;
    if (t >= NUM_GRAPHS * OUTDIM) return;
    int g = t / OUTDIM, o = t % OUTDIM;
    float c = fmaxf(g_gcnt[g], 1.0f);
    float inv = 1.0f / c;
    float acc = bc[o];
#pragma unroll 8
    for (int k = 0; k < HIDDEN; k++)
        acc += g_gsum[g * HIDDEN + k] * inv * Wc[k * OUTDIM + o];
    out[t] = acc;
}

// ---------------- launch -------------------------------------------------------
extern "C" void kernel_launch(void* const* d_in, const int* in_sizes, int n_in,
                              void* d_out, int out_size) {
    const float* features = (const float*)d_in[0];
    const void*  src      = d_in[1];
    const void*  dst      = d_in[2];
    const void*  gids     = d_in[3];
    const float* W1 = (const float*)d_in[4];
    const float* b1 = (const float*)d_in[5];
    const float* W2 = (const float*)d_in[6];
    const float* b2 = (const float*)d_in[7];
    const float* W3 = (const float*)d_in[8];
    const float* b3 = (const float*)d_in[9];
    const float* Wc = (const float*)d_in[10];
    const float* bc = (const float*)d_in[11];
    float* out = (float*)d_out;

    uint32_t* ah;  cudaGetSymbolAddress((void**)&ah, g_ah);
    float* h;      cudaGetSymbolAddress((void**)&h, g_h);
    uint32_t* whi; cudaGetSymbolAddress((void**)&whi, g_whi);
    uint32_t* wlo; cudaGetSymbolAddress((void**)&wlo, g_wlo);

    cudaFuncSetAttribute(gemm_tc_kernel,
                         cudaFuncAttributeMaxDynamicSharedMemorySize, GEMM_SMEM_BYTES);

    detect_kernel<<<1, 32>>>((const unsigned int*)src);
    prep_kernel<<<N_NODES / 256, 256>>>(W1, W2, W3);
    build_kernel<<<N_EDGES / 256, 256>>>(src, dst);

    const int GATHER_BLOCKS = (N_NODES * 32) / 256;
    const int WSZ = HIDDEN * 64;

    gather_kernel<<<GATHER_BLOCKS, 256>>>(features, ah);
    gemm_tc_kernel<<<GEMM_GRID, 256, GEMM_SMEM_BYTES>>>(ah, whi, wlo, b1, h);
    gather_kernel<<<GATHER_BLOCKS, 256>>>(h, ah);
    gemm_tc_kernel<<<GEMM_GRID, 256, GEMM_SMEM_BYTES>>>(ah, whi + WSZ, wlo + WSZ, b2, h);
    gather_kernel<<<GATHER_BLOCKS, 256>>>(h, ah);
    gemm_tc_kernel<<<GEMM_GRID, 256, GEMM_SMEM_BYTES>>>(ah, whi + 2 * WSZ, wlo + 2 * WSZ, b3, h);

    readout_kernel<<<N_NODES / 128, 128>>>(h, gids);
    classifier_kernel<<<1, NUM_GRAPHS * OUTDIM>>>(Wc, bc, out);
}

// round 12
// speedup vs baseline: 1.8437x; 1.0837x over previous
#include <cuda_runtime.h>
#include <cuda_fp16.h>
#include <math.h>
#include <stdint.h>

#define N_NODES 65536
#define N_EDGES 524288
#define HIDDEN 128
#define OUTDIM 10
#define NUM_GRAPHS 64
#define SLOT_CAP 64

// ---------------- scratch (device globals; no allocation allowed) ----------
// fp16 node features / hidden states: 64 words (128 fp16) per row
__device__ __align__(16) static uint32_t g_h16[(size_t)N_NODES * 64];
// A plane: fp16 pairs, k-word-permuted
__device__ __align__(16) static uint32_t g_ah[(size_t)N_NODES * 64];
__device__ static int      g_deg[N_NODES];
__device__ static int      g_slots[(size_t)N_NODES * SLOT_CAP];
__device__ static float    g_gsum[NUM_GRAPHS * HIDDEN];
__device__ static float    g_gcnt[NUM_GRAPHS];
__device__ static int      g_is64;
// W plane: [layer][n*64 + permuted k word], fp16 pairs
__device__ __align__(16) static uint32_t g_w16[3][HIDDEN * 64];

// ---------------- helpers ----------------------------------------------------
__device__ __forceinline__ int kperm(int w) {
    return (w & ~7) | (((w & 3) << 1) | ((w >> 2) & 1));
}

__device__ __forceinline__ float elu_fast(float v) {
    return v > 0.0f ? v : (__expf(v) - 1.0f);
}

__device__ __forceinline__ uint32_t pack_h2(float a, float b) {
    __half2 h = __floats2half2_rn(a, b);
    return *reinterpret_cast<uint32_t*>(&h);
}

__device__ __forceinline__ void mma_fp16(float* c, uint32_t a0, uint32_t a1,
                                         uint32_t a2, uint32_t a3,
                                         uint32_t b0, uint32_t b1) {
    asm volatile(
        "mma.sync.aligned.m16n8k16.row.col.f32.f16.f16.f32 "
        "{%0,%1,%2,%3}, {%4,%5,%6,%7}, {%8,%9}, {%0,%1,%2,%3};"
        : "+f"(c[0]), "+f"(c[1]), "+f"(c[2]), "+f"(c[3])
        : "r"(a0), "r"(a1), "r"(a2), "r"(a3), "r"(b0), "r"(b1));
}

// ---------------- index dtype detection (1 warp, parallel) -------------------
__global__ void detect_kernel(const unsigned int* __restrict__ w) {
    int lane = threadIdx.x;
    bool zero = true;
#pragma unroll
    for (int j = 0; j < 4; j++) {
        if (w[1 + 2 * (lane + 32 * j)] != 0u) zero = false;
    }
    unsigned int mask = __ballot_sync(0xffffffffu, zero);
    if (lane == 0) g_is64 = (mask == 0xffffffffu) ? 1 : 0;
}

__device__ __forceinline__ int load_idx(const void* p, int i, int is64) {
    if (is64) return (int)((const long long*)p)[i];
    return ((const int*)p)[i];
}

// ---------------- prep: zero scratch + W fp16 + features fp16 ----------------
// grid covers 2M threads: features convert (4 floats/thread) + small tasks
__global__ void prep_kernel(const float* __restrict__ features,
                            const float* __restrict__ W1,
                            const float* __restrict__ W2,
                            const float* __restrict__ W3) {
    int i = blockIdx.x * blockDim.x + threadIdx.x;
    if (i < N_NODES) g_deg[i] = 0;
    if (i < NUM_GRAPHS * HIDDEN) g_gsum[i] = 0.0f;
    if (i < NUM_GRAPHS) g_gcnt[i] = 0.0f;
    if (i < 3 * HIDDEN * 64) {
        int layer = i / (HIDDEN * 64);
        int rem = i - layer * (HIDDEN * 64);
        int n = rem >> 6, w = rem & 63;
        const float* W = (layer == 0) ? W1 : (layer == 1) ? W2 : W3;
        float v0 = __ldg(W + (2 * w) * HIDDEN + n);
        float v1 = __ldg(W + (2 * w + 1) * HIDDEN + n);
        g_w16[layer][n * 64 + kperm(w)] = pack_h2(v0, v1);
    }
    if (i < (N_NODES * HIDDEN) / 4) {
        float4 f = __ldg((const float4*)features + i);
        uint2 u;
        u.x = pack_h2(f.x, f.y);
        u.y = pack_h2(f.z, f.w);
        *((uint2*)g_h16 + i) = u;
    }
}

// ---------------- bucketed inverse adjacency ---------------------------------
__global__ void build_kernel(const void* __restrict__ src,
                             const void* __restrict__ dst) {
    int e = blockIdx.x * blockDim.x + threadIdx.x;
    if (e >= N_EDGES) return;
    int is64 = g_is64;
    int d = load_idx(dst, e, is64);
    int s = load_idx(src, e, is64);
    int pos = atomicAdd(&g_deg[d], 1);
    if (pos < SLOT_CAP) g_slots[(size_t)d * SLOT_CAP + pos] = s;
}

// ---------------- gather-sum over fp16 rows -> fp16 A plane (permuted) -------
__global__ void gather_kernel(const uint32_t* __restrict__ h16,
                              uint32_t* __restrict__ ah) {
    int w = (blockIdx.x * blockDim.x + threadIdx.x) >> 5;
    int lane = threadIdx.x & 31;
    if (w >= N_NODES) return;
    int deg = g_deg[w];
    if (deg > SLOT_CAP) deg = SLOT_CAP;
    const int* slots = g_slots + (size_t)w * SLOT_CAP;
    int s0 = (lane < deg) ? slots[lane] : 0;
    int s1 = (32 + lane < deg) ? slots[32 + lane] : 0;
    float4 acc = make_float4(0.f, 0.f, 0.f, 0.f);
    for (int i = 0; i < deg; i++) {
        int s = __shfl_sync(0xffffffffu, (i < 32) ? s0 : s1, i & 31);
        uint2 u = __ldg((const uint2*)(h16 + (size_t)s * 64) + lane);
        float2 f01 = __half22float2(*reinterpret_cast<__half2*>(&u.x));
        float2 f23 = __half22float2(*reinterpret_cast<__half2*>(&u.y));
        acc.x += f01.x; acc.y += f01.y; acc.z += f23.x; acc.w += f23.y;
    }
    size_t rowOff = (size_t)w * 64;
    ah[rowOff + kperm(2 * lane)]     = pack_h2(acc.x, acc.y);
    ah[rowOff + kperm(2 * lane + 1)] = pack_h2(acc.z, acc.w);
}

// ---------------- persistent single-pass fp16 mma GEMM ------------------------
// 444 CTAs (3/SM target) loop over 64-row tiles. 8 warps (2M x 4N), warp 32x32.
#define AS_STR 68
#define SM_AH 0
#define SM_WH (64 * AS_STR)
#define GEMM_SMEM_WORDS ((64 + 128) * AS_STR)
#define GEMM_SMEM_BYTES (GEMM_SMEM_WORDS * 4)
#define GEMM_GRID 444
#define NUM_TILES (N_NODES / 64)

__global__ void __launch_bounds__(256, 3)
gemm_tc_kernel(const uint32_t* __restrict__ Ah,
               const uint32_t* __restrict__ Wp,
               const float* __restrict__ b, uint32_t* __restrict__ out16) {
    extern __shared__ __align__(16) uint32_t smem[];
    int tid = threadIdx.x;
    int lane = tid & 31, wid = tid >> 5;
    int gq = lane >> 2, tq = lane & 3;
    int warp_m = wid & 1, warp_n = wid >> 1;
    const int mBase = warp_m * 32;
    const int nBase = warp_n * 32;

    // ---- stage W plane once ----
    {
        const uint4* src = (const uint4*)Wp;
        for (int i = tid; i < 128 * 16; i += 256) {
            int n = i >> 4, c4 = i & 15;
            *(uint4*)(smem + SM_WH + n * AS_STR + c4 * 4) = __ldg(src + i);
        }
    }

    int tile = blockIdx.x;
    uint4 pa[4];
    if (tile < NUM_TILES) {
        const uint4* src = (const uint4*)(Ah + (size_t)tile * 64 * 64);
#pragma unroll
        for (int j = 0; j < 4; j++) pa[j] = __ldg(src + tid + 256 * j);
    }
    __syncthreads();

    while (tile < NUM_TILES) {
        // ---- commit prefetched A to SMEM ----
#pragma unroll
        for (int j = 0; j < 4; j++) {
            int i = tid + 256 * j;
            int r = i >> 4, c4 = i & 15;
            *(uint4*)(smem + SM_AH + r * AS_STR + c4 * 4) = pa[j];
        }
        __syncthreads();

        // ---- prefetch next tile's A (overlaps mainloop) ----
        int next = tile + GEMM_GRID;
        if (next < NUM_TILES) {
            const uint4* src = (const uint4*)(Ah + (size_t)next * 64 * 64);
#pragma unroll
            for (int j = 0; j < 4; j++) pa[j] = __ldg(src + tid + 256 * j);
        }

        float acc[2][4][4];
#pragma unroll
        for (int mi = 0; mi < 2; mi++)
#pragma unroll
            for (int ni = 0; ni < 4; ni++)
#pragma unroll
                for (int r = 0; r < 4; r++) acc[mi][ni][r] = 0.0f;

#pragma unroll
        for (int ks = 0; ks < 8; ks++) {
            int kw = ks * 8 + 2 * tq;
            uint2 ah2[2][2];
#pragma unroll
            for (int mi = 0; mi < 2; mi++) {
                int r = mBase + mi * 16 + gq;
                ah2[mi][0] = *(const uint2*)(smem + SM_AH + r * AS_STR + kw);
                ah2[mi][1] = *(const uint2*)(smem + SM_AH + (r + 8) * AS_STR + kw);
            }
            uint2 bh[4];
#pragma unroll
            for (int ni = 0; ni < 4; ni++) {
                int c = nBase + ni * 8 + gq;
                bh[ni] = *(const uint2*)(smem + SM_WH + c * AS_STR + kw);
            }
#pragma unroll
            for (int mi = 0; mi < 2; mi++)
#pragma unroll
                for (int ni = 0; ni < 4; ni++)
                    mma_fp16(acc[mi][ni], ah2[mi][0].x, ah2[mi][1].x, ah2[mi][0].y, ah2[mi][1].y,
                             bh[ni].x, bh[ni].y);
        }

        // ---- epilogue: bias + fast ELU + fp16 store ----
        size_t rowBase = (size_t)tile * 64;
#pragma unroll
        for (int mi = 0; mi < 2; mi++) {
            int r0 = mBase + mi * 16 + gq;
#pragma unroll
            for (int ni = 0; ni < 4; ni++) {
                int c0 = nBase + ni * 8 + 2 * tq;
                float2 bb = __ldg((const float2*)(b + c0));
                float v0 = elu_fast(acc[mi][ni][0] + bb.x);
                float v1 = elu_fast(acc[mi][ni][1] + bb.y);
                float v2 = elu_fast(acc[mi][ni][2] + bb.x);
                float v3 = elu_fast(acc[mi][ni][3] + bb.y);
                out16[(rowBase + r0) * 64 + (c0 >> 1)] = pack_h2(v0, v1);
                out16[(rowBase + r0 + 8) * 64 + (c0 >> 1)] = pack_h2(v2, v3);
            }
        }
        __syncthreads();
        tile = next;
    }
}

// ---------------- graph readout (fp16 h, sums + counts fused) -----------------
__global__ void readout_kernel(const uint32_t* __restrict__ h16,
                               const void* __restrict__ gid) {
    int t = threadIdx.x;
    int base = blockIdx.x * 128;
    int is64 = g_is64;
    const __half* hh = (const __half*)h16;
    int cur = load_idx(gid, base, is64);
    float acc = 0.0f;
    int runlen = 0;
    for (int n = 0; n < 128; n++) {
        int node = base + n;
        int g = load_idx(gid, node, is64);
        if (g != cur) {
            atomicAdd(&g_gsum[cur * HIDDEN + t], acc);
            if (t == 0) atomicAdd(&g_gcnt[cur], (float)runlen);
            acc = 0.0f; runlen = 0; cur = g;
        }
        acc += __half2float(hh[(size_t)node * HIDDEN + t]);
        runlen++;
    }
    atomicAdd(&g_gsum[cur * HIDDEN + t], acc);
    if (t == 0) atomicAdd(&g_gcnt[cur], (float)runlen);
}

__global__ void classifier_kernel(const float* __restrict__ Wc,
                                  const float* __restrict__ bc,
                                  float* __restrict__ out) {
    int t = blockIdx.x * blockDim.x + threadIdx.x;
    if (t >= NUM_GRAPHS * OUTDIM) return;
    int g = t / OUTDIM, o = t % OUTDIM;
    float c = fmaxf(g_gcnt[g], 1.0f);
    float inv = 1.0f / c;
    float acc = bc[o];
#pragma unroll 8
    for (int k = 0; k < HIDDEN; k++)
        acc += g_gsum[g * HIDDEN + k] * inv * Wc[k * OUTDIM + o];
    out[t] = acc;
}

// ---------------- launch -------------------------------------------------------
extern "C" void kernel_launch(void* const* d_in, const int* in_sizes, int n_in,
                              void* d_out, int out_size) {
    const float* features = (const float*)d_in[0];
    const void*  src      = d_in[1];
    const void*  dst      = d_in[2];
    const void*  gids     = d_in[3];
    const float* W1 = (const float*)d_in[4];
    const float* b1 = (const float*)d_in[5];
    const float* W2 = (const float*)d_in[6];
    const float* b2 = (const float*)d_in[7];
    const float* W3 = (const float*)d_in[8];
    const float* b3 = (const float*)d_in[9];
    const float* Wc = (const float*)d_in[10];
    const float* bc = (const float*)d_in[11];
    float* out = (float*)d_out;

    uint32_t* h16; cudaGetSymbolAddress((void**)&h16, g_h16);
    uint32_t* ah;  cudaGetSymbolAddress((void**)&ah, g_ah);
    uint32_t* w16; cudaGetSymbolAddress((void**)&w16, g_w16);

    cudaFuncSetAttribute(gemm_tc_kernel,
                         cudaFuncAttributeMaxDynamicSharedMemorySize, GEMM_SMEM_BYTES);

    detect_kernel<<<1, 32>>>((const unsigned int*)src);
    prep_kernel<<<(N_NODES * HIDDEN / 4) / 256, 256>>>(features, W1, W2, W3);
    build_kernel<<<N_EDGES / 256, 256>>>(src, dst);

    const int GATHER_BLOCKS = (N_NODES * 32) / 256;
    const int WSZ = HIDDEN * 64;

    gather_kernel<<<GATHER_BLOCKS, 256>>>(h16, ah);
    gemm_tc_kernel<<<GEMM_GRID, 256, GEMM_SMEM_BYTES>>>(ah, w16, b1, h16);
    gather_kernel<<<GATHER_BLOCKS, 256>>>(h16, ah);
    gemm_tc_kernel<<<GEMM_GRID, 256, GEMM_SMEM_BYTES>>>(ah, w16 + WSZ, b2, h16);
    gather_kernel<<<GATHER_BLOCKS, 256>>>(h16, ah);
    gemm_tc_kernel<<<GEMM_GRID, 256, GEMM_SMEM_BYTES>>>(ah, w16 + 2 * WSZ, b3, h16);

    readout_kernel<<<N_NODES / 128, 128>>>(h16, gids);
    classifier_kernel<<<1, NUM_GRAPHS * OUTDIM>>>(Wc, bc, out);
}